// round 1
// baseline (speedup 1.0000x reference)
#include <cuda_runtime.h>

#define B_  4
#define C_  19
#define HI  64
#define WI  128
#define HO  512
#define WO  1024
#define NPIX (B_*HO*WO)
#define REPS 32

// ---------------- device scratch (no allocations allowed) ----------------
__device__ float g_prob[2][NPIX];
__device__ float g_nll [2][NPIX];
__device__ unsigned g_hist0[REPS][2][2048];
__device__ unsigned g_hist1[2][2048];
__device__ unsigned g_hist2[2][1024];
__device__ unsigned g_prefix[2];
__device__ int      g_krem[2];
__device__ float    g_thr[2];
__device__ double   g_sum[2];
__device__ unsigned long long g_cnt[2];
__device__ int      g_posc[B_], g_negc[B_];
__device__ double   g_bce;

// ---------------- reduce helpers ----------------
__device__ __forceinline__ double warpReduceD(double v) {
    #pragma unroll
    for (int o = 16; o > 0; o >>= 1) v += __shfl_down_sync(0xffffffffu, v, o);
    return v;
}
__device__ __forceinline__ int warpReduceI(int v) {
    #pragma unroll
    for (int o = 16; o > 0; o >>= 1) v += __shfl_down_sync(0xffffffffu, v, o);
    return v;
}

// ---------------- init ----------------
__global__ void init_kernel(int kidx) {
    int i = blockIdx.x * blockDim.x + threadIdx.x;
    int stride = gridDim.x * blockDim.x;
    unsigned* h0 = &g_hist0[0][0][0];
    for (int j = i; j < REPS * 2 * 2048; j += stride) h0[j] = 0;
    unsigned* h1 = &g_hist1[0][0];
    for (int j = i; j < 2 * 2048; j += stride) h1[j] = 0;
    unsigned* h2 = &g_hist2[0][0];
    for (int j = i; j < 2 * 1024; j += stride) h2[j] = 0;
    if (i < 2) {
        g_prefix[i] = 0;
        g_krem[i] = kidx;
        g_thr[i] = 0.7f;
        g_sum[i] = 0.0;
        g_cnt[i] = 0ULL;
    }
    if (i < B_) { g_posc[i] = 0; g_negc[i] = 0; }
    if (i == 0) g_bce = 0.0;
}

// ---------------- fused upsample + log_softmax + prob/nll + hist L0 ----------------
__global__ __launch_bounds__(256) void compute_kernel(
    const float* __restrict__ mainp,
    const float* __restrict__ coarsep,
    const int*   __restrict__ seg)
{
    __shared__ float rowv[2][C_][36];

    const float SY = (float)(HI - 1) / (float)(HO - 1);
    const float SX = (float)(WI - 1) / (float)(WO - 1);

    int oy = blockIdx.y;
    int b  = blockIdx.z;
    int xs = blockIdx.x * 256;

    float fy = oy * SY;
    int   y0 = (int)floorf(fy);
    int   y1 = min(y0 + 1, HI - 1);
    float wy = fy - (float)y0;

    int xbase = (int)floorf((float)xs * SX);
    int xlast = (int)floorf((float)(xs + 255) * SX);
    int xmax  = min(xlast + 1, WI - 1);
    int ncols = xmax - xbase + 1;   // <= 34

    const float* p0 = mainp   + (size_t)b * C_ * HI * WI;
    const float* p1 = coarsep + (size_t)b * C_ * HI * WI;

    for (int idx = threadIdx.x; idx < C_ * ncols; idx += 256) {
        int c  = idx / ncols;
        int xo = idx - c * ncols;
        int xi = xbase + xo;
        int o0 = c * HI * WI + y0 * WI + xi;
        int o1 = c * HI * WI + y1 * WI + xi;
        float a0 = p0[o0], a1 = p0[o1];
        rowv[0][c][xo] = a0 + wy * (a1 - a0);
        float b0 = p1[o0], b1 = p1[o1];
        rowv[1][c][xo] = b0 + wy * (b1 - b0);
    }
    __syncthreads();

    int   ox  = xs + threadIdx.x;
    float fx  = (float)ox * SX;
    int   x0  = (int)floorf(fx);
    float wx  = fx - (float)x0;
    int   x1  = min(x0 + 1, WI - 1);
    int   i0  = x0 - xbase;
    int   i1  = x1 - xbase;

    int pix = (b * HO + oy) * WO + ox;
    int t   = seg[pix];
    bool valid = (t != 255);
    int  tc = valid ? min(t, C_ - 1) : 0;

    unsigned rep = (blockIdx.x + gridDim.x * (blockIdx.y + gridDim.y * blockIdx.z)) & (REPS - 1);

    #pragma unroll
    for (int l = 0; l < 2; l++) {
        float v[C_];
        float m = -1e30f;
        float vt = 0.0f;
        #pragma unroll
        for (int c = 0; c < C_; c++) {
            float a  = rowv[l][c][i0];
            float bb = rowv[l][c][i1];
            float val = a + wx * (bb - a);
            v[c] = val;
            m = fmaxf(m, val);
            if (c == tc) vt = val;
        }
        float s = 0.0f;
        #pragma unroll
        for (int c = 0; c < C_; c++) s += __expf(v[c] - m);
        float lse  = m + __logf(s);
        float logp = vt - lse;
        float prob = valid ? __expf(logp) : 1.0f;
        float nl   = valid ? fmaxf(-logp, 0.0f) : -1.0f;
        g_prob[l][pix] = prob;
        g_nll [l][pix] = nl;
        atomicAdd(&g_hist0[rep][l][__float_as_uint(prob) >> 21], 1u);
    }
}

// ---------------- radix-select scan (one block per loss) ----------------
__global__ void scan_kernel(int level) {
    int l  = blockIdx.x;
    int nb = (level == 2) ? 1024 : 2048;
    __shared__ unsigned s[2048];
    int tid = threadIdx.x;

    for (int i = tid; i < nb; i += 1024) {
        unsigned v;
        if (level == 0) {
            v = 0;
            #pragma unroll
            for (int r = 0; r < REPS; r++) v += g_hist0[r][l][i];
        } else if (level == 1) {
            v = g_hist1[l][i];
        } else {
            v = g_hist2[l][i];
        }
        s[i] = v;
    }
    __syncthreads();

    // inclusive Hillis-Steele scan
    for (int off = 1; off < nb; off <<= 1) {
        unsigned tmp[2];
        int j = 0;
        for (int i = tid; i < nb; i += 1024, j++)
            tmp[j] = (i >= off) ? s[i - off] : 0u;
        __syncthreads();
        j = 0;
        for (int i = tid; i < nb; i += 1024, j++)
            s[i] += tmp[j];
        __syncthreads();
    }

    int k = g_krem[l];
    __syncthreads();   // everyone has read k before anyone writes it

    for (int i = tid; i < nb; i += 1024) {
        unsigned cum    = s[i];
        unsigned before = (i == 0) ? 0u : s[i - 1];
        if ((int)cum > k && (int)before <= k) {
            if (level == 0) {
                g_prefix[l] = (unsigned)i;
            } else if (level == 1) {
                g_prefix[l] = (g_prefix[l] << 11) | (unsigned)i;
            } else {
                unsigned bits = (g_prefix[l] << 10) | (unsigned)i;
                g_thr[l] = fmaxf(0.7f, __uint_as_float(bits));
            }
            g_krem[l] = k - (int)before;
        }
    }
}

// ---------------- refine histograms (levels 1, 2) ----------------
__global__ void hist_refine(int level) {
    int l = blockIdx.y;
    unsigned pref = g_prefix[l];
    int stride = gridDim.x * blockDim.x;
    for (int i = blockIdx.x * blockDim.x + threadIdx.x; i < NPIX; i += stride) {
        unsigned bits = __float_as_uint(g_prob[l][i]);
        if (level == 1) {
            if ((bits >> 21) == pref)
                atomicAdd(&g_hist1[l][(bits >> 10) & 0x7FFu], 1u);
        } else {
            if ((bits >> 10) == pref)
                atomicAdd(&g_hist2[l][bits & 0x3FFu], 1u);
        }
    }
}

// ---------------- OHEM final reduction ----------------
__global__ void ohem_reduce() {
    int l = blockIdx.y;
    float thr = g_thr[l];
    double lsum = 0.0;
    int    lcnt = 0;
    int stride = gridDim.x * blockDim.x;
    for (int i = blockIdx.x * blockDim.x + threadIdx.x; i < NPIX; i += stride) {
        float p  = g_prob[l][i];
        float nl = g_nll[l][i];
        if (nl >= 0.0f && p <= thr) { lsum += (double)nl; lcnt++; }
    }
    double wd = warpReduceD(lsum);
    int    wi = warpReduceI(lcnt);
    __shared__ double sd[8];
    __shared__ int    si[8];
    int warp = threadIdx.x >> 5, lane = threadIdx.x & 31;
    if (lane == 0) { sd[warp] = wd; si[warp] = wi; }
    __syncthreads();
    if (warp == 0) {
        int nw = blockDim.x >> 5;
        double d = (lane < nw) ? sd[lane] : 0.0;
        int    c = (lane < nw) ? si[lane] : 0;
        d = warpReduceD(d);
        c = warpReduceI(c);
        if (lane == 0) {
            atomicAdd(&g_sum[l], d);
            atomicAdd(&g_cnt[l], (unsigned long long)c);
        }
    }
}

// ---------------- boundary: per-sample pos/neg counts ----------------
__global__ void bcount_kernel(const float* __restrict__ bgt) {
    int b = blockIdx.y;
    const float* p = bgt + (size_t)b * HO * WO;
    int lp = 0, ln = 0;
    int stride = gridDim.x * blockDim.x;
    for (int i = blockIdx.x * blockDim.x + threadIdx.x; i < HO * WO; i += stride) {
        float t = p[i];
        lp += (t == 1.0f);
        ln += (t == 0.0f);
    }
    int wp = warpReduceI(lp);
    int wn = warpReduceI(ln);
    __shared__ int sp[8], sn[8];
    int warp = threadIdx.x >> 5, lane = threadIdx.x & 31;
    if (lane == 0) { sp[warp] = wp; sn[warp] = wn; }
    __syncthreads();
    if (warp == 0) {
        int nw = blockDim.x >> 5;
        int a = (lane < nw) ? sp[lane] : 0;
        int c = (lane < nw) ? sn[lane] : 0;
        a = warpReduceI(a);
        c = warpReduceI(c);
        if (lane == 0) {
            atomicAdd(&g_posc[b], a);
            atomicAdd(&g_negc[b], c);
        }
    }
}

// ---------------- boundary BCE (fused upsample + weighted BCE mean) ----------------
__global__ __launch_bounds__(256) void bce_kernel(
    const float* __restrict__ bp,
    const float* __restrict__ bgt)
{
    const float SY = (float)(HI - 1) / (float)(HO - 1);
    const float SX = (float)(WI - 1) / (float)(WO - 1);
    int b  = blockIdx.z;
    int oy = blockIdx.y;
    int ox = blockIdx.x * blockDim.x + threadIdx.x;

    float fy = oy * SY;
    int   y0 = (int)floorf(fy);
    int   y1 = min(y0 + 1, HI - 1);
    float wy = fy - (float)y0;
    float fx = (float)ox * SX;
    int   x0 = (int)floorf(fx);
    int   x1 = min(x0 + 1, WI - 1);
    float wx = fx - (float)x0;

    const float* base = bp + (size_t)b * HI * WI;
    float v00 = base[y0 * WI + x0], v01 = base[y0 * WI + x1];
    float v10 = base[y1 * WI + x0], v11 = base[y1 * WI + x1];
    float top = v00 + wx * (v01 - v00);
    float bot = v10 + wx * (v11 - v10);
    float p   = top + wy * (bot - top);

    float t = bgt[((size_t)b * HO + oy) * WO + ox];
    float pos = (float)g_posc[b], neg = (float)g_negc[b];
    float validc = pos + neg;
    float w = (t == 1.0f) ? (neg / validc) : ((t == 0.0f) ? (pos / validc) : 0.0f);

    float lp  = fmaxf(__logf(p), -100.0f);
    float l1p = fmaxf(__logf(1.0f - p), -100.0f);
    float val = w * (-(t * lp + (1.0f - t) * l1p));

    double d = warpReduceD((double)val);
    __shared__ double sd[8];
    int warp = threadIdx.x >> 5, lane = threadIdx.x & 31;
    if (lane == 0) sd[warp] = d;
    __syncthreads();
    if (warp == 0) {
        int nw = blockDim.x >> 5;
        double dd = (lane < nw) ? sd[lane] : 0.0;
        dd = warpReduceD(dd);
        if (lane == 0) atomicAdd(&g_bce, dd);
    }
}

// ---------------- finalize ----------------
__global__ void finalize_kernel(float* out) {
    unsigned long long c0 = g_cnt[0]; if (c0 < 1ULL) c0 = 1ULL;
    unsigned long long c1 = g_cnt[1]; if (c1 < 1ULL) c1 = 1ULL;
    double loss = g_sum[0] / (double)c0
                + g_sum[1] / (double)c1
                + g_bce / (double)NPIX;
    out[0] = (float)loss;
}

// ---------------- launch ----------------
extern "C" void kernel_launch(void* const* d_in, const int* in_sizes, int n_in,
                              void* d_out, int out_size)
{
    const float* mainp   = (const float*)d_in[0];
    const float* coarsep = (const float*)d_in[1];
    const float* bp      = (const float*)d_in[2];
    const int*   seg     = (const int*)d_in[3];
    const float* bgt     = (const float*)d_in[4];

    int nseg = in_sizes[3];
    int kidx = ((nseg < 100000) ? nseg : 100000) - 1;

    init_kernel<<<128, 256>>>(kidx);
    compute_kernel<<<dim3(WO / 256, HO, B_), 256>>>(mainp, coarsep, seg);
    bcount_kernel<<<dim3(64, B_), 256>>>(bgt);
    scan_kernel<<<2, 1024>>>(0);
    hist_refine<<<dim3(512, 2), 256>>>(1);
    scan_kernel<<<2, 1024>>>(1);
    hist_refine<<<dim3(512, 2), 256>>>(2);
    scan_kernel<<<2, 1024>>>(2);
    ohem_reduce<<<dim3(1024, 2), 256>>>();
    bce_kernel<<<dim3(WO / 256, HO, B_), 256>>>(bp, bgt);
    finalize_kernel<<<1, 1>>>((float*)d_out);
}

// round 2
// speedup vs baseline: 2.3271x; 2.3271x over previous
#include <cuda_runtime.h>

#define B_   4
#define C_   19
#define HI   64
#define WI   128
#define HO   512
#define WO   1024
#define NPIX (B_*HO*WO)
#define LOG2E 1.4426950408889634f
#define LN2f  0.6931471805599453f

// ---------------- device scratch (no allocations allowed) ----------------
__device__ float g_oh[2][2][64];     // [loss][{cnt,sum}][slot]
__device__ float g_bce4[B_][4][32];  // [sample][{S1,S0,pos,neg}][slot]
__device__ int   g_m[2];             // compacted count per loss (probs > 0.7)
__device__ uint2 g_comp[2][NPIX];    // {prob_bits, nll_bits or -1e30 sentinel}
__device__ float g_extraSum[2];      // fallback corrections (thr > 0.7 case)
__device__ float g_extraCnt[2];

// ---------------- init ----------------
__global__ void init_kernel() {
    int i = threadIdx.x;
    float* oh = &g_oh[0][0][0];
    for (int j = i; j < 2 * 2 * 64; j += blockDim.x) oh[j] = 0.f;
    float* bb = &g_bce4[0][0][0];
    for (int j = i; j < B_ * 4 * 32; j += blockDim.x) bb[j] = 0.f;
    if (i < 2) { g_m[i] = 0; g_extraSum[i] = 0.f; g_extraCnt[i] = 0.f; }
}

// ---------------- fused: upsample + softmax + OHEM accumulate + compaction + BCE ----------------
__global__ __launch_bounds__(256) void compute_kernel(
    const float* __restrict__ mainp,
    const float* __restrict__ coarsep,
    const int*   __restrict__ seg,
    const float* __restrict__ bp,
    const float* __restrict__ bgt)
{
    __shared__ float rowv[2][C_][40];
    __shared__ float sred[8][8];

    const float SY = 63.f / 511.f;
    const float SX = 127.f / 1023.f;

    int oy = blockIdx.y;
    int b  = blockIdx.z;
    int xs = blockIdx.x * 256;

    float fy = oy * SY;
    int   y0 = (int)fy;
    int   y1 = min(y0 + 1, HI - 1);
    float wy = fy - (float)y0;

    int xbase = (int)((float)xs * SX);
    int xlast = (int)((float)(xs + 255) * SX);
    int ntot  = xlast + 2 - xbase;   // columns [xbase, xlast+1]

    const float* p0 = mainp   + (size_t)b * C_ * HI * WI;
    const float* p1 = coarsep + (size_t)b * C_ * HI * WI;

    for (int idx = threadIdx.x; idx < C_ * ntot; idx += 256) {
        int c  = idx / ntot;
        int xo = idx - c * ntot;
        int xi = min(xbase + xo, WI - 1);
        int o0 = c * HI * WI + y0 * WI + xi;
        int o1 = c * HI * WI + y1 * WI + xi;
        float a0 = p0[o0], a1 = p0[o1];
        rowv[0][c][xo] = fmaf(wy, a1 - a0, a0) * LOG2E;
        float b0 = p1[o0], b1 = p1[o1];
        rowv[1][c][xo] = fmaf(wy, b1 - b0, b0) * LOG2E;
    }
    __syncthreads();

    int   ox = xs + threadIdx.x;
    float fx = (float)ox * SX;
    int   x0 = (int)fx;
    float wx = fx - (float)x0;
    int   i0 = x0 - xbase;

    int  pix   = (b * HO + oy) * WO + ox;
    int  t     = seg[pix];
    bool valid = (t != 255);
    int  tc    = valid ? t : 0;
    if (tc >= C_) tc = C_ - 1;

    int lane = threadIdx.x & 31;
    float r0 = 0.f, r1 = 0.f, r2 = 0.f, r3 = 0.f;

    #pragma unroll
    for (int l = 0; l < 2; l++) {
        float s = 0.f;
        #pragma unroll
        for (int c = 0; c < C_; c++) {
            float a  = rowv[l][c][i0];
            float bb = rowv[l][c][i0 + 1];
            s += exp2f(fmaf(wx, bb - a, a));
        }
        float a   = rowv[l][tc][i0];
        float bb  = rowv[l][tc][i0 + 1];
        float vt  = fmaf(wx, bb - a, a);
        float lp2 = vt - __log2f(s);        // log2(prob at target)
        float prob = exp2f(lp2);
        float nll  = -lp2 * LN2f;
        if (!valid) prob = 1.0f;

        bool le = valid && (prob <= 0.7f);
        if (l == 0) { r0 = le ? 1.f : 0.f; r1 = le ? nll : 0.f; }
        else        { r2 = le ? 1.f : 0.f; r3 = le ? nll : 0.f; }

        bool gtt = prob > 0.7f;
        unsigned ball = __ballot_sync(0xffffffffu, gtt);
        if (ball) {
            int ldr = __ffs(ball) - 1;
            int base = 0;
            if (lane == ldr) base = atomicAdd(&g_m[l], __popc(ball));
            base = __shfl_sync(0xffffffffu, base, ldr);
            if (gtt) {
                int rank = __popc(ball & ((1u << lane) - 1u));
                g_comp[l][base + rank] =
                    make_uint2(__float_as_uint(prob),
                               __float_as_uint(valid ? nll : -1e30f));
            }
        }
    }

    // ---- boundary BCE (fused) ----
    float tb = bgt[pix];
    const float* pb = bp + (size_t)b * HI * WI;
    int x1 = min(x0 + 1, WI - 1);
    float v00 = pb[y0 * WI + x0], v01 = pb[y0 * WI + x1];
    float v10 = pb[y1 * WI + x0], v11 = pb[y1 * WI + x1];
    float top = fmaf(wx, v01 - v00, v00);
    float bot = fmaf(wx, v11 - v10, v10);
    float p   = fmaf(wy, bot - top, top);

    float r4 = 0.f, r5 = 0.f, r6 = 0.f, r7 = 0.f;
    if (tb == 1.0f)      { r6 = 1.f; r4 = -fmaxf(__logf(p), -100.f); }
    else if (tb == 0.0f) { r7 = 1.f; r5 = -fmaxf(__logf(1.f - p), -100.f); }

    // ---- block reduce 8 quantities ----
    #pragma unroll
    for (int o = 16; o > 0; o >>= 1) {
        r0 += __shfl_down_sync(~0u, r0, o); r1 += __shfl_down_sync(~0u, r1, o);
        r2 += __shfl_down_sync(~0u, r2, o); r3 += __shfl_down_sync(~0u, r3, o);
        r4 += __shfl_down_sync(~0u, r4, o); r5 += __shfl_down_sync(~0u, r5, o);
        r6 += __shfl_down_sync(~0u, r6, o); r7 += __shfl_down_sync(~0u, r7, o);
    }
    int warp = threadIdx.x >> 5;
    if (lane == 0) {
        sred[warp][0] = r0; sred[warp][1] = r1; sred[warp][2] = r2; sred[warp][3] = r3;
        sred[warp][4] = r4; sred[warp][5] = r5; sred[warp][6] = r6; sred[warp][7] = r7;
    }
    __syncthreads();
    if (threadIdx.x < 8) {
        float acc = 0.f;
        #pragma unroll
        for (int w = 0; w < 8; w++) acc += sred[w][threadIdx.x];
        int q   = threadIdx.x;
        int blk = blockIdx.x + 4 * (blockIdx.y + 512 * blockIdx.z);
        if (q < 4) atomicAdd(&g_oh[q >> 1][q & 1][blk & 63], acc);
        else       atomicAdd(&g_bce4[b][q - 4][blk & 31], acc);
    }
}

// ---------------- fallback: exact kth select when count(prob<=0.7) < K ----------------
__global__ __launch_bounds__(1024) void fallback_kernel(int K) {
    __shared__ unsigned hist[2048];
    __shared__ int      s_r;
    __shared__ unsigned s_pref;
    __shared__ int      s_cle;
    __shared__ float    redS[32], redC[32];
    int tid = threadIdx.x, lane = tid & 31, w = tid >> 5;

    for (int l = 0; l < 2; l++) {
        if (tid == 0) {
            float cl = 0.f;
            #pragma unroll
            for (int i = 0; i < 64; i++) cl += g_oh[l][0][i];
            s_cle = (int)(cl + 0.5f);
        }
        __syncthreads();
        int cLE = s_cle;
        __syncthreads();
        if (cLE >= K) continue;            // common path: thr = 0.7, nothing to do

        int m = g_m[l];
        if (tid == 0) { s_r = K - 1 - cLE; s_pref = 0u; }
        __syncthreads();

        #pragma unroll
        for (int lev = 0; lev < 3; lev++) {
            for (int i = tid; i < 2048; i += 1024) hist[i] = 0u;
            __syncthreads();
            unsigned pref = s_pref;
            for (int i = tid; i < m; i += 1024) {
                unsigned bits = g_comp[l][i].x;
                bool ok; unsigned bin;
                if (lev == 0)      { ok = true;                  bin = bits >> 21; }
                else if (lev == 1) { ok = (bits >> 21) == pref;  bin = (bits >> 10) & 0x7FFu; }
                else               { ok = (bits >> 10) == pref;  bin = bits & 0x3FFu; }
                if (ok) atomicAdd(&hist[bin], 1u);
            }
            __syncthreads();
            if (tid == 0) {
                int rr = s_r; unsigned cum = 0u;
                int nb = (lev == 2) ? 1024 : 2048;
                for (int i2 = 0; i2 < nb; i2++) {
                    unsigned h = hist[i2];
                    if ((int)(cum + h) > rr) {
                        s_pref = (lev == 0) ? (unsigned)i2
                               : (lev == 1) ? ((pref << 11) | (unsigned)i2)
                                            : ((pref << 10) | (unsigned)i2);
                        s_r = rr - (int)cum;
                        break;
                    }
                    cum += h;
                }
            }
            __syncthreads();
        }
        unsigned thr_bits = s_pref;   // exact kth value's bit pattern (> 0.7)

        float es = 0.f, ec = 0.f;
        for (int i = tid; i < m; i += 1024) {
            uint2 e = g_comp[l][i];
            float nl = __uint_as_float(e.y);
            if (e.x <= thr_bits && nl > -1e29f) { es += nl; ec += 1.f; }
        }
        #pragma unroll
        for (int o = 16; o > 0; o >>= 1) {
            es += __shfl_down_sync(~0u, es, o);
            ec += __shfl_down_sync(~0u, ec, o);
        }
        if (lane == 0) { redS[w] = es; redC[w] = ec; }
        __syncthreads();
        if (tid == 0) {
            float ts = 0.f, tc2 = 0.f;
            #pragma unroll
            for (int i = 0; i < 32; i++) { ts += redS[i]; tc2 += redC[i]; }
            g_extraSum[l] = ts; g_extraCnt[l] = tc2;
        }
        __syncthreads();
    }
}

// ---------------- finalize ----------------
__global__ __launch_bounds__(128) void finalize_kernel(float* out) {
    int tid = threadIdx.x, lane = tid & 31, w = tid >> 5;
    __shared__ double shb[4];
    __shared__ float  shoh[2][4];

    float bs1  = g_bce4[w][0][lane];
    float bs0  = g_bce4[w][1][lane];
    float bpos = g_bce4[w][2][lane];
    float bneg = g_bce4[w][3][lane];
    float oc = 0.f, os = 0.f, oc1 = 0.f, os1 = 0.f;
    if (w < 2) {
        oc  = g_oh[0][0][tid]; os  = g_oh[0][1][tid];
        oc1 = g_oh[1][0][tid]; os1 = g_oh[1][1][tid];
    }
    #pragma unroll
    for (int o = 16; o > 0; o >>= 1) {
        bs1 += __shfl_down_sync(~0u, bs1, o); bs0 += __shfl_down_sync(~0u, bs0, o);
        bpos += __shfl_down_sync(~0u, bpos, o); bneg += __shfl_down_sync(~0u, bneg, o);
        oc += __shfl_down_sync(~0u, oc, o); os += __shfl_down_sync(~0u, os, o);
        oc1 += __shfl_down_sync(~0u, oc1, o); os1 += __shfl_down_sync(~0u, os1, o);
    }
    if (lane == 0) {
        double denom = (double)bpos + (double)bneg;
        shb[w] = ((double)bneg * (double)bs1 + (double)bpos * (double)bs0) / denom;
        if (w < 2) { shoh[w][0] = oc; shoh[w][1] = os; shoh[w][2] = oc1; shoh[w][3] = os1; }
    }
    __syncthreads();
    if (tid == 0) {
        double cnt0 = (double)shoh[0][0] + (double)shoh[1][0] + (double)g_extraCnt[0];
        double sum0 = (double)shoh[0][1] + (double)shoh[1][1] + (double)g_extraSum[0];
        double cnt1 = (double)shoh[0][2] + (double)shoh[1][2] + (double)g_extraCnt[1];
        double sum1 = (double)shoh[0][3] + (double)shoh[1][3] + (double)g_extraSum[1];
        if (cnt0 < 1.0) cnt0 = 1.0;
        if (cnt1 < 1.0) cnt1 = 1.0;
        double bce = (shb[0] + shb[1] + shb[2] + shb[3]) / (double)NPIX;
        out[0] = (float)(sum0 / cnt0 + sum1 / cnt1 + bce);
    }
}

// ---------------- launch ----------------
extern "C" void kernel_launch(void* const* d_in, const int* in_sizes, int n_in,
                              void* d_out, int out_size)
{
    const float* mainp   = (const float*)d_in[0];
    const float* coarsep = (const float*)d_in[1];
    const float* bp      = (const float*)d_in[2];
    const int*   seg     = (const int*)d_in[3];
    const float* bgt     = (const float*)d_in[4];

    int nseg = in_sizes[3];
    int K = (nseg < 100000) ? nseg : 100000;

    init_kernel<<<1, 512>>>();
    compute_kernel<<<dim3(WO / 256, HO, B_), 256>>>(mainp, coarsep, seg, bp, bgt);
    fallback_kernel<<<1, 1024>>>(K);
    finalize_kernel<<<1, 128>>>((float*)d_out);
}